// round 5
// baseline (speedup 1.0000x reference)
#include <cuda_runtime.h>
#include <math.h>

// Problem constants
#define T_TOKENS 16384   // B*L = 4*4096
#define DDIM     1024
#define NEXP     8
#define TM 64
#define TN 64
#define TK 16

// ---------------- scratch (static device globals; no allocation) ------------
__device__ int   g_count[NEXP];                 // tokens routed to each expert
__device__ int   g_base[NEXP];                  // exclusive prefix of counts
__device__ int   g_tok[NEXP][T_TOKENS];         // token index per slot
__device__ float g_w  [NEXP][T_TOKENS];         // routing weight per slot
__device__ float g_H  [2 * T_TOKENS * DDIM];    // packed hidden activations (128 MB)

// ---------------- init ------------------------------------------------------
__global__ void init_counts_kernel() {
    if (threadIdx.x < NEXP) g_count[threadIdx.x] = 0;
}

// ---------------- router: logits -> top2 -> renormalized weights ------------
// one warp per token, 8 tokens per block
__global__ void router_kernel(const float* __restrict__ x,
                              const float* __restrict__ Wr) {
    __shared__ __align__(16) float sWr[NEXP * DDIM];   // 32 KB
    for (int i = threadIdx.x; i < NEXP * DDIM; i += blockDim.x) sWr[i] = Wr[i];
    __syncthreads();

    const int warp = threadIdx.x >> 5;
    const int lane = threadIdx.x & 31;
    const int t = blockIdx.x * 8 + warp;            // token id, grid covers exactly T

    const float4* xr = (const float4*)(x + (size_t)t * DDIM);
    const float4* wr = (const float4*)sWr;

    float acc[NEXP];
#pragma unroll
    for (int e = 0; e < NEXP; e++) acc[e] = 0.f;

    for (int i = lane; i < DDIM / 4; i += 32) {
        float4 xv = xr[i];
#pragma unroll
        for (int e = 0; e < NEXP; e++) {
            float4 wv = wr[e * (DDIM / 4) + i];
            acc[e] += xv.x * wv.x + xv.y * wv.y + xv.z * wv.z + xv.w * wv.w;
        }
    }
#pragma unroll
    for (int e = 0; e < NEXP; e++)
#pragma unroll
        for (int off = 16; off; off >>= 1)
            acc[e] += __shfl_xor_sync(0xffffffffu, acc[e], off);

    if (lane == 0) {
        // top-1
        int i1 = 0; float m1 = acc[0];
#pragma unroll
        for (int e = 1; e < NEXP; e++)
            if (acc[e] > m1) { m1 = acc[e]; i1 = e; }
        // top-2 (lowest index wins ties, matching top_k)
        int i2 = -1; float m2 = -INFINITY;
#pragma unroll
        for (int e = 0; e < NEXP; e++)
            if (e != i1 && acc[e] > m2) { m2 = acc[e]; i2 = e; }

        // softmax over {m1,m2} == softmax over all, renormalized to top-2
        float w1 = 1.0f / (1.0f + expf(m2 - m1));
        float w2 = 1.0f - w1;

        int p1 = atomicAdd(&g_count[i1], 1);
        g_tok[i1][p1] = t; g_w[i1][p1] = w1;
        int p2 = atomicAdd(&g_count[i2], 1);
        g_tok[i2][p2] = t; g_w[i2][p2] = w2;
    }
}

__global__ void prefix_kernel() {
    if (threadIdx.x == 0) {
        int s = 0;
#pragma unroll
        for (int e = 0; e < NEXP; e++) { g_base[e] = s; s += g_count[e]; }
    }
}

// ---------------- GEMM1: H = gelu(Xg @ W1[e]^T + b1[e]) ---------------------
// A: gathered token rows of x   [cnt, D]
// B: W1[e]  (row f, col d) row-major  -> C[m, f] = sum_d A[m,d] * W1[f,d]
__global__ void __launch_bounds__(256)
gemm1_kernel(const float* __restrict__ x,
             const float* __restrict__ W1,
             const float* __restrict__ b1) {
    const int e    = blockIdx.z;
    const int cnt  = g_count[e];
    const int row0 = blockIdx.y * TM;
    if (row0 >= cnt) return;
    const int col0 = blockIdx.x * TN;
    const int base = g_base[e];

    __shared__ __align__(16) float As[TK][TM + 4];
    __shared__ __align__(16) float Bs[TK][TN + 4];
    __shared__ int sTok[TM];

    const int tid = threadIdx.x;
    if (tid < TM) {
        int r = row0 + tid;
        sTok[tid] = g_tok[e][min(r, cnt - 1)];
    }
    __syncthreads();

    const int tx = tid & 15, ty = tid >> 4;
    const int lrow = tid >> 2;           // 0..63
    const int lk4  = (tid & 3) * 4;      // 0,4,8,12

    const size_t arow  = (size_t)sTok[lrow] * DDIM;
    const float* Bbase = W1 + ((size_t)e * DDIM + (col0 + lrow)) * DDIM;

    float c[4][4];
#pragma unroll
    for (int i = 0; i < 4; i++)
#pragma unroll
        for (int j = 0; j < 4; j++) c[i][j] = 0.f;

    for (int k0 = 0; k0 < DDIM; k0 += TK) {
        float4 av = *(const float4*)(x + arow + k0 + lk4);
        float4 bv = *(const float4*)(Bbase + k0 + lk4);
        __syncthreads();
        As[lk4 + 0][lrow] = av.x; As[lk4 + 1][lrow] = av.y;
        As[lk4 + 2][lrow] = av.z; As[lk4 + 3][lrow] = av.w;
        Bs[lk4 + 0][lrow] = bv.x; Bs[lk4 + 1][lrow] = bv.y;
        Bs[lk4 + 2][lrow] = bv.z; Bs[lk4 + 3][lrow] = bv.w;
        __syncthreads();
#pragma unroll
        for (int k = 0; k < TK; k++) {
            float4 a = *(const float4*)&As[k][ty * 4];
            float4 b = *(const float4*)&Bs[k][tx * 4];
            c[0][0] += a.x * b.x; c[0][1] += a.x * b.y; c[0][2] += a.x * b.z; c[0][3] += a.x * b.w;
            c[1][0] += a.y * b.x; c[1][1] += a.y * b.y; c[1][2] += a.y * b.z; c[1][3] += a.y * b.w;
            c[2][0] += a.z * b.x; c[2][1] += a.z * b.y; c[2][2] += a.z * b.z; c[2][3] += a.z * b.w;
            c[3][0] += a.w * b.x; c[3][1] += a.w * b.y; c[3][2] += a.w * b.z; c[3][3] += a.w * b.w;
        }
    }

#pragma unroll
    for (int i = 0; i < 4; i++) {
        int r = row0 + ty * 4 + i;
        if (r < cnt) {
            float* hrow = g_H + (size_t)(base + r) * DDIM;
#pragma unroll
            for (int j = 0; j < 4; j++) {
                int f = col0 + tx * 4 + j;
                float v = c[i][j] + b1[e * DDIM + f];
                // exact gelu: 0.5*v*(1+erf(v/sqrt(2)))
                hrow[f] = 0.5f * v * (1.0f + erff(v * 0.70710678118654752f));
            }
        }
    }
}

// ---------------- GEMM2: out[tok] += w * (H @ W2[e]^T + b2[e]) ---------------
// A: packed H rows [cnt, D];  B: W2[e] (row d, col f) -> C[m, d] = sum_f H[m,f]*W2[d,f]
__global__ void __launch_bounds__(256)
gemm2_kernel(const float* __restrict__ W2,
             const float* __restrict__ b2,
             float* __restrict__ out) {
    const int e    = blockIdx.z;
    const int cnt  = g_count[e];
    const int row0 = blockIdx.y * TM;
    if (row0 >= cnt) return;
    const int col0 = blockIdx.x * TN;
    const int base = g_base[e];

    __shared__ __align__(16) float As[TK][TM + 4];
    __shared__ __align__(16) float Bs[TK][TN + 4];

    const int tid = threadIdx.x;
    const int tx = tid & 15, ty = tid >> 4;
    const int lrow = tid >> 2;
    const int lk4  = (tid & 3) * 4;

    const int rA = min(row0 + lrow, cnt - 1);
    const float* Abase = g_H + (size_t)(base + rA) * DDIM;
    const float* Bbase = W2 + ((size_t)e * DDIM + (col0 + lrow)) * DDIM;

    float c[4][4];
#pragma unroll
    for (int i = 0; i < 4; i++)
#pragma unroll
        for (int j = 0; j < 4; j++) c[i][j] = 0.f;

    for (int k0 = 0; k0 < DDIM; k0 += TK) {
        float4 av = *(const float4*)(Abase + k0 + lk4);
        float4 bv = *(const float4*)(Bbase + k0 + lk4);
        __syncthreads();
        As[lk4 + 0][lrow] = av.x; As[lk4 + 1][lrow] = av.y;
        As[lk4 + 2][lrow] = av.z; As[lk4 + 3][lrow] = av.w;
        Bs[lk4 + 0][lrow] = bv.x; Bs[lk4 + 1][lrow] = bv.y;
        Bs[lk4 + 2][lrow] = bv.z; Bs[lk4 + 3][lrow] = bv.w;
        __syncthreads();
#pragma unroll
        for (int k = 0; k < TK; k++) {
            float4 a = *(const float4*)&As[k][ty * 4];
            float4 b = *(const float4*)&Bs[k][tx * 4];
            c[0][0] += a.x * b.x; c[0][1] += a.x * b.y; c[0][2] += a.x * b.z; c[0][3] += a.x * b.w;
            c[1][0] += a.y * b.x; c[1][1] += a.y * b.y; c[1][2] += a.y * b.z; c[1][3] += a.y * b.w;
            c[2][0] += a.z * b.x; c[2][1] += a.z * b.y; c[2][2] += a.z * b.z; c[2][3] += a.z * b.w;
            c[3][0] += a.w * b.x; c[3][1] += a.w * b.y; c[3][2] += a.w * b.z; c[3][3] += a.w * b.w;
        }
    }

#pragma unroll
    for (int i = 0; i < 4; i++) {
        int r = row0 + ty * 4 + i;
        if (r < cnt) {
            int   tok = g_tok[e][r];
            float w   = g_w[e][r];
            float* orow = out + (size_t)tok * DDIM;
#pragma unroll
            for (int j = 0; j < 4; j++) {
                int dcol = col0 + tx * 4 + j;
                float y = c[i][j] + b2[e * DDIM + dcol];
                atomicAdd(&orow[dcol], w * y);
            }
        }
    }
}

// ---------------- launch -----------------------------------------------------
extern "C" void kernel_launch(void* const* d_in, const int* in_sizes, int n_in,
                              void* d_out, int out_size) {
    const float* x  = (const float*)d_in[0];
    const float* Wr = (const float*)d_in[1];
    const float* W1 = (const float*)d_in[2];
    const float* b1 = (const float*)d_in[3];
    const float* W2 = (const float*)d_in[4];
    const float* b2 = (const float*)d_in[5];
    float* out = (float*)d_out;

    init_counts_kernel<<<1, 32>>>();
    router_kernel<<<T_TOKENS / 8, 256>>>(x, Wr);
    prefix_kernel<<<1, 32>>>();
    cudaMemsetAsync(d_out, 0, (size_t)out_size * sizeof(float), 0);

    dim3 grid(DDIM / TN, T_TOKENS / TM, NEXP);   // (16, 256, 8), early-exit on count
    gemm1_kernel<<<grid, 256>>>(x, W1, b1);
    gemm2_kernel<<<grid, 256>>>(W2, b2, out);
}

// round 8
// speedup vs baseline: 2.9788x; 2.9788x over previous
#include <cuda_runtime.h>
#include <cuda_bf16.h>
#include <math.h>
#include <stdint.h>

// Problem constants
#define T_TOKENS 16384
#define DDIM     1024
#define NEXP     8

// GEMM tiling
#define BM 128
#define BN 64
#define BK 32
#define LDR 40   // bf16 elems per smem row: 32 data + 8 pad = 80B stride

// ---------------- scratch (static device globals; no allocation) ------------
__device__ int    g_count[NEXP];
__device__ int    g_base[NEXP];
__device__ int    g_tok[NEXP][T_TOKENS];
__device__ int4   g_assign[T_TOKENS];
__device__ float2 g_tw[T_TOKENS];
__device__ float  g_H[2 * T_TOKENS * DDIM];
__device__ float  g_Y[2 * T_TOKENS * DDIM];

// ---------------- init ------------------------------------------------------
__global__ void init_counts_kernel() {
    if (threadIdx.x < NEXP) {
        g_count[threadIdx.x] = 0;
    }
}

// ---------------- router ----------------------------------------------------
__global__ void router_kernel(const float* __restrict__ x,
                              const float* __restrict__ Wr) {
    __shared__ __align__(16) float sWr[NEXP * DDIM];
    for (int i = threadIdx.x; i < NEXP * DDIM; i += blockDim.x) {
        sWr[i] = Wr[i];
    }
    __syncthreads();

    const int warp = threadIdx.x >> 5;
    const int lane = threadIdx.x & 31;
    const int t = blockIdx.x * 8 + warp;

    const float4* xr = (const float4*)(x + (size_t)t * DDIM);
    const float4* wr = (const float4*)sWr;

    float acc[NEXP];
#pragma unroll
    for (int e = 0; e < NEXP; e++) {
        acc[e] = 0.f;
    }

    for (int i = lane; i < DDIM / 4; i += 32) {
        float4 xv = xr[i];
#pragma unroll
        for (int e = 0; e < NEXP; e++) {
            float4 wv = wr[e * (DDIM / 4) + i];
            acc[e] += xv.x * wv.x + xv.y * wv.y + xv.z * wv.z + xv.w * wv.w;
        }
    }
#pragma unroll
    for (int e = 0; e < NEXP; e++) {
#pragma unroll
        for (int off = 16; off; off >>= 1) {
            acc[e] += __shfl_xor_sync(0xffffffffu, acc[e], off);
        }
    }

    if (lane == 0) {
        int i1 = 0;
        float m1 = acc[0];
#pragma unroll
        for (int e = 1; e < NEXP; e++) {
            if (acc[e] > m1) { m1 = acc[e]; i1 = e; }
        }
        int i2 = -1;
        float m2 = -INFINITY;
#pragma unroll
        for (int e = 0; e < NEXP; e++) {
            if (e != i1 && acc[e] > m2) { m2 = acc[e]; i2 = e; }
        }

        float w1 = 1.0f / (1.0f + expf(m2 - m1));
        float w2 = 1.0f - w1;

        int p1 = atomicAdd(&g_count[i1], 1);
        g_tok[i1][p1] = t;
        int p2 = atomicAdd(&g_count[i2], 1);
        g_tok[i2][p2] = t;
        g_assign[t] = make_int4(i1, p1, i2, p2);
        g_tw[t] = make_float2(w1, w2);
    }
}

__global__ void prefix_kernel() {
    if (threadIdx.x == 0) {
        int s = 0;
#pragma unroll
        for (int e = 0; e < NEXP; e++) {
            g_base[e] = s;
            s += g_count[e];
        }
    }
}

// ---------------- helpers ----------------------------------------------------
static __device__ __forceinline__ void ldsm4(uint32_t* r, const __nv_bfloat16* p) {
    uint32_t a = (uint32_t)__cvta_generic_to_shared(p);
    asm volatile("ldmatrix.sync.aligned.m8n8.x4.shared.b16 {%0,%1,%2,%3}, [%4];"
                 : "=r"(r[0]), "=r"(r[1]), "=r"(r[2]), "=r"(r[3])
                 : "r"(a));
}

static __device__ __forceinline__ void mma16816(float* c, const uint32_t* a, const uint32_t* b) {
    asm volatile("mma.sync.aligned.m16n8k16.row.col.f32.bf16.bf16.f32 "
                 "{%0,%1,%2,%3},{%4,%5,%6,%7},{%8,%9},{%0,%1,%2,%3};"
                 : "+f"(c[0]), "+f"(c[1]), "+f"(c[2]), "+f"(c[3])
                 : "r"(a[0]), "r"(a[1]), "r"(a[2]), "r"(a[3]),
                   "r"(b[0]), "r"(b[1]));
}

static __device__ __forceinline__ uint32_t pk2(__nv_bfloat16 a, __nv_bfloat16 b) {
    __nv_bfloat162 t = __halves2bfloat162(a, b);
    return *reinterpret_cast<uint32_t*>(&t);
}

// split float4 into hi/lo bf16 pairs and store 8B each to smem (off in bf16 elems)
static __device__ __forceinline__ void split_store(__nv_bfloat16* sh, __nv_bfloat16* sl,
                                                   int off, float4 v) {
    __nv_bfloat16 h0 = __float2bfloat16_rn(v.x);
    __nv_bfloat16 h1 = __float2bfloat16_rn(v.y);
    __nv_bfloat16 h2 = __float2bfloat16_rn(v.z);
    __nv_bfloat16 h3 = __float2bfloat16_rn(v.w);
    __nv_bfloat16 l0 = __float2bfloat16_rn(v.x - __bfloat162float(h0));
    __nv_bfloat16 l1 = __float2bfloat16_rn(v.y - __bfloat162float(h1));
    __nv_bfloat16 l2 = __float2bfloat16_rn(v.z - __bfloat162float(h2));
    __nv_bfloat16 l3 = __float2bfloat16_rn(v.w - __bfloat162float(h3));
    uint2 hv;
    hv.x = pk2(h0, h1);
    hv.y = pk2(h2, h3);
    uint2 lv;
    lv.x = pk2(l0, l1);
    lv.y = pk2(l2, l3);
    *reinterpret_cast<uint2*>(sh + off) = hv;
    *reinterpret_cast<uint2*>(sl + off) = lv;
}

// ============================================================================
// GEMM1: g_H[base+r][f] = gelu( sum_d x[tok[r]][d] * W1[e][f][d] + b1[e][f] )
// ============================================================================
__global__ void __launch_bounds__(256, 2)
gemm1_kernel(const float* __restrict__ x,
             const float* __restrict__ W1,
             const float* __restrict__ b1) {
    const int e    = blockIdx.z;
    const int cnt  = g_count[e];
    const int row0 = blockIdx.y * BM;
    if (row0 >= cnt) { return; }
    const int col0 = blockIdx.x * BN;
    const int base = g_base[e];

    __shared__ __nv_bfloat16 sAh[BM * LDR];
    __shared__ __nv_bfloat16 sAl[BM * LDR];
    __shared__ __nv_bfloat16 sBh[BN * LDR];
    __shared__ __nv_bfloat16 sBl[BN * LDR];
    __shared__ int sRow[BM];

    const int tid  = threadIdx.x;
    const int lane = tid & 31;
    const int wid  = tid >> 5;

    if (tid < BM) {
        int r = row0 + tid;
        if (r >= cnt) { r = cnt - 1; }
        sRow[tid] = g_tok[e][r];
    }
    __syncthreads();

    const int arow = tid >> 3;   // 0..31
    const int ac4  = tid & 7;    // float4 index within 32-wide k slab

    const size_t aG0 = (size_t)sRow[arow]      * DDIM + ac4 * 4;
    const size_t aG1 = (size_t)sRow[arow + 32] * DDIM + ac4 * 4;
    const size_t aG2 = (size_t)sRow[arow + 64] * DDIM + ac4 * 4;
    const size_t aG3 = (size_t)sRow[arow + 96] * DDIM + ac4 * 4;
    const float* Bg = W1 + ((size_t)e * DDIM + col0) * DDIM;
    const size_t bG0 = (size_t)(arow)      * DDIM + ac4 * 4;
    const size_t bG1 = (size_t)(arow + 32) * DDIM + ac4 * 4;

    const int sA0 = (arow)      * LDR + ac4 * 4;
    const int sA1 = (arow + 32) * LDR + ac4 * 4;
    const int sA2 = (arow + 64) * LDR + ac4 * 4;
    const int sA3 = (arow + 96) * LDR + ac4 * 4;

    const int wm = (wid & 3) * 32;
    const int wn = (wid >> 2) * 32;
    const int aLd = (wm + (lane & 15)) * LDR + ((lane >> 4) << 3);
    const int bLd = (wn + ((lane >> 4) << 3) + (lane & 7)) * LDR + (lane & 8);

    float acc[2][4][4];
#pragma unroll
    for (int i = 0; i < 2; i++) {
#pragma unroll
        for (int j = 0; j < 4; j++) {
#pragma unroll
            for (int q = 0; q < 4; q++) {
                acc[i][j][q] = 0.f;
            }
        }
    }

    float4 pa0 = *(const float4*)(x + aG0);
    float4 pa1 = *(const float4*)(x + aG1);
    float4 pa2 = *(const float4*)(x + aG2);
    float4 pa3 = *(const float4*)(x + aG3);
    float4 pb0 = *(const float4*)(Bg + bG0);
    float4 pb1 = *(const float4*)(Bg + bG1);
    split_store(sAh, sAl, sA0, pa0);
    split_store(sAh, sAl, sA1, pa1);
    split_store(sAh, sAl, sA2, pa2);
    split_store(sAh, sAl, sA3, pa3);
    split_store(sBh, sBl, sA0, pb0);
    split_store(sBh, sBl, sA1, pb1);
    __syncthreads();

    for (int k0 = 0; k0 < DDIM; k0 += BK) {
        const int kn = k0 + BK;
        if (kn < DDIM) {
            pa0 = *(const float4*)(x + aG0 + kn);
            pa1 = *(const float4*)(x + aG1 + kn);
            pa2 = *(const float4*)(x + aG2 + kn);
            pa3 = *(const float4*)(x + aG3 + kn);
            pb0 = *(const float4*)(Bg + bG0 + kn);
            pb1 = *(const float4*)(Bg + bG1 + kn);
        }

#pragma unroll
        for (int kk = 0; kk < BK; kk += 16) {
            uint32_t ah0[4];
            uint32_t ah1[4];
            uint32_t al0[4];
            uint32_t al1[4];
            uint32_t bh0[4];
            uint32_t bh1[4];
            uint32_t bl0[4];
            uint32_t bl1[4];
            ldsm4(ah0, sAh + aLd + kk);
            ldsm4(ah1, sAh + aLd + 16 * LDR + kk);
            ldsm4(al0, sAl + aLd + kk);
            ldsm4(al1, sAl + aLd + 16 * LDR + kk);
            ldsm4(bh0, sBh + bLd + kk);
            ldsm4(bh1, sBh + bLd + 16 * LDR + kk);
            ldsm4(bl0, sBl + bLd + kk);
            ldsm4(bl1, sBl + bLd + 16 * LDR + kk);

            mma16816(acc[0][0], ah0, &bh0[0]);
            mma16816(acc[0][1], ah0, &bh0[2]);
            mma16816(acc[0][2], ah0, &bh1[0]);
            mma16816(acc[0][3], ah0, &bh1[2]);
            mma16816(acc[1][0], ah1, &bh0[0]);
            mma16816(acc[1][1], ah1, &bh0[2]);
            mma16816(acc[1][2], ah1, &bh1[0]);
            mma16816(acc[1][3], ah1, &bh1[2]);

            mma16816(acc[0][0], ah0, &bl0[0]);
            mma16816(acc[0][1], ah0, &bl0[2]);
            mma16816(acc[0][2], ah0, &bl1[0]);
            mma16816(acc[0][3], ah0, &bl1[2]);
            mma16816(acc[1][0], ah1, &bl0[0]);
            mma16816(acc[1][1], ah1, &bl0[2]);
            mma16816(acc[1][2], ah1, &bl1[0]);
            mma16816(acc[1][3], ah1, &bl1[2]);

            mma16816(acc[0][0], al0, &bh0[0]);
            mma16816(acc[0][1], al0, &bh0[2]);
            mma16816(acc[0][2], al0, &bh1[0]);
            mma16816(acc[0][3], al0, &bh1[2]);
            mma16816(acc[1][0], al1, &bh0[0]);
            mma16816(acc[1][1], al1, &bh0[2]);
            mma16816(acc[1][2], al1, &bh1[0]);
            mma16816(acc[1][3], al1, &bh1[2]);
        }

        if (kn < DDIM) {
            __syncthreads();
            split_store(sAh, sAl, sA0, pa0);
            split_store(sAh, sAl, sA1, pa1);
            split_store(sAh, sAl, sA2, pa2);
            split_store(sAh, sAl, sA3, pa3);
            split_store(sBh, sBl, sA0, pb0);
            split_store(sBh, sBl, sA1, pb1);
            __syncthreads();
        }
    }

    const int r0l = lane >> 2;
    const int c0l = (lane & 3) * 2;
#pragma unroll
    for (int mt = 0; mt < 2; mt++) {
#pragma unroll
        for (int nt = 0; nt < 4; nt++) {
            const int fc = col0 + wn + nt * 8 + c0l;
#pragma unroll
            for (int half = 0; half < 2; half++) {
                const int r = row0 + wm + mt * 16 + r0l + half * 8;
                if (r < cnt) {
                    float v0 = acc[mt][nt][half * 2 + 0];
                    float v1 = acc[mt][nt][half * 2 + 1];
                    float2 bb = *(const float2*)(b1 + (size_t)e * DDIM + fc);
                    v0 += bb.x;
                    v1 += bb.y;
                    v0 = 0.5f * v0 * (1.0f + erff(v0 * 0.70710678118654752f));
                    v1 = 0.5f * v1 * (1.0f + erff(v1 * 0.70710678118654752f));
                    *(float2*)(g_H + (size_t)(base + r) * DDIM + fc) = make_float2(v0, v1);
                }
            }
        }
    }
}

// ============================================================================
// GEMM2: g_Y[base+r][d] = sum_f g_H[base+r][f] * W2[e][d][f]
// ============================================================================
__global__ void __launch_bounds__(256, 2)
gemm2_kernel(const float* __restrict__ W2) {
    const int e    = blockIdx.z;
    const int cnt  = g_count[e];
    const int row0 = blockIdx.y * BM;
    if (row0 >= cnt) { return; }
    const int col0 = blockIdx.x * BN;
    const int base = g_base[e];

    __shared__ __nv_bfloat16 sAh[BM * LDR];
    __shared__ __nv_bfloat16 sAl[BM * LDR];
    __shared__ __nv_bfloat16 sBh[BN * LDR];
    __shared__ __nv_bfloat16 sBl[BN * LDR];

    const int tid  = threadIdx.x;
    const int lane = tid & 31;
    const int wid  = tid >> 5;

    const int arow = tid >> 3;
    const int ac4  = tid & 7;

    int r0c = row0 + arow;
    int r1c = row0 + arow + 32;
    int r2c = row0 + arow + 64;
    int r3c = row0 + arow + 96;
    if (r0c >= cnt) { r0c = cnt - 1; }
    if (r1c >= cnt) { r1c = cnt - 1; }
    if (r2c >= cnt) { r2c = cnt - 1; }
    if (r3c >= cnt) { r3c = cnt - 1; }

    const float* Asrc = g_H;
    const size_t aG0 = (size_t)(base + r0c) * DDIM + ac4 * 4;
    const size_t aG1 = (size_t)(base + r1c) * DDIM + ac4 * 4;
    const size_t aG2 = (size_t)(base + r2c) * DDIM + ac4 * 4;
    const size_t aG3 = (size_t)(base + r3c) * DDIM + ac4 * 4;
    const float* Bg = W2 + ((size_t)e * DDIM + col0) * DDIM;
    const size_t bG0 = (size_t)(arow)      * DDIM + ac4 * 4;
    const size_t bG1 = (size_t)(arow + 32) * DDIM + ac4 * 4;

    const int sA0 = (arow)      * LDR + ac4 * 4;
    const int sA1 = (arow + 32) * LDR + ac4 * 4;
    const int sA2 = (arow + 64) * LDR + ac4 * 4;
    const int sA3 = (arow + 96) * LDR + ac4 * 4;

    const int wm = (wid & 3) * 32;
    const int wn = (wid >> 2) * 32;
    const int aLd = (wm + (lane & 15)) * LDR + ((lane >> 4) << 3);
    const int bLd = (wn + ((lane >> 4) << 3) + (lane & 7)) * LDR + (lane & 8);

    float acc[2][4][4];
#pragma unroll
    for (int i = 0; i < 2; i++) {
#pragma unroll
        for (int j = 0; j < 4; j++) {
#pragma unroll
            for (int q = 0; q < 4; q++) {
                acc[i][j][q] = 0.f;
            }
        }
    }

    float4 pa0 = *(const float4*)(Asrc + aG0);
    float4 pa1 = *(const float4*)(Asrc + aG1);
    float4 pa2 = *(const float4*)(Asrc + aG2);
    float4 pa3 = *(const float4*)(Asrc + aG3);
    float4 pb0 = *(const float4*)(Bg + bG0);
    float4 pb1 = *(const float4*)(Bg + bG1);
    split_store(sAh, sAl, sA0, pa0);
    split_store(sAh, sAl, sA1, pa1);
    split_store(sAh, sAl, sA2, pa2);
    split_store(sAh, sAl, sA3, pa3);
    split_store(sBh, sBl, sA0, pb0);
    split_store(sBh, sBl, sA1, pb1);
    __syncthreads();

    for (int k0 = 0; k0 < DDIM; k0 += BK) {
        const int kn = k0 + BK;
        if (kn < DDIM) {
            pa0 = *(const float4*)(Asrc + aG0 + kn);
            pa1 = *(const float4*)(Asrc + aG1 + kn);
            pa2 = *(const float4*)(Asrc + aG2 + kn);
            pa3 = *(const float4*)(Asrc + aG3 + kn);
            pb0 = *(const float4*)(Bg + bG0 + kn);
            pb1 = *(const float4*)(Bg + bG1 + kn);
        }

#pragma unroll
        for (int kk = 0; kk < BK; kk += 16) {
            uint32_t ah0[4];
            uint32_t ah1[4];
            uint32_t al0[4];
            uint32_t al1[4];
            uint32_t bh0[4];
            uint32_t bh1[4];
            uint32_t bl0[4];
            uint32_t bl1[4];
            ldsm4(ah0, sAh + aLd + kk);
            ldsm4(ah1, sAh + aLd + 16 * LDR + kk);
            ldsm4(al0, sAl + aLd + kk);
            ldsm4(al1, sAl + aLd + 16 * LDR + kk);
            ldsm4(bh0, sBh + bLd + kk);
            ldsm4(bh1, sBh + bLd + 16 * LDR + kk);
            ldsm4(bl0, sBl + bLd + kk);
            ldsm4(bl1, sBl + bLd + 16 * LDR + kk);

            mma16816(acc[0][0], ah0, &bh0[0]);
            mma16816(acc[0][1], ah0, &bh0[2]);
            mma16816(acc[0][2], ah0, &bh1[0]);
            mma16816(acc[0][3], ah0, &bh1[2]);
            mma16816(acc[1][0], ah1, &bh0[0]);
            mma16816(acc[1][1], ah1, &bh0[2]);
            mma16816(acc[1][2], ah1, &bh1[0]);
            mma16816(acc[1][3], ah1, &bh1[2]);

            mma16816(acc[0][0], ah0, &bl0[0]);
            mma16816(acc[0][1], ah0, &bl0[2]);
            mma16816(acc[0][2], ah0, &bl1[0]);
            mma16816(acc[0][3], ah0, &bl1[2]);
            mma16816(acc[1][0], ah1, &bl0[0]);
            mma16816(acc[1][1], ah1, &bl0[2]);
            mma16816(acc[1][2], ah1, &bl1[0]);
            mma16816(acc[1][3], ah1, &bl1[2]);

            mma16816(acc[0][0], al0, &bh0[0]);
            mma16816(acc[0][1], al0, &bh0[2]);
            mma16816(acc[0][2], al0, &bh1[0]);
            mma16816(acc[0][3], al0, &bh1[2]);
            mma16816(acc[1][0], al1, &bh0[0]);
            mma16816(acc[1][1], al1, &bh0[2]);
            mma16816(acc[1][2], al1, &bh1[0]);
            mma16816(acc[1][3], al1, &bh1[2]);
        }

        if (kn < DDIM) {
            __syncthreads();
            split_store(sAh, sAl, sA0, pa0);
            split_store(sAh, sAl, sA1, pa1);
            split_store(sAh, sAl, sA2, pa2);
            split_store(sAh, sAl, sA3, pa3);
            split_store(sBh, sBl, sA0, pb0);
            split_store(sBh, sBl, sA1, pb1);
            __syncthreads();
        }
    }

    const int r0l = lane >> 2;
    const int c0l = (lane & 3) * 2;
#pragma unroll
    for (int mt = 0; mt < 2; mt++) {
#pragma unroll
        for (int nt = 0; nt < 4; nt++) {
            const int fc = col0 + wn + nt * 8 + c0l;
#pragma unroll
            for (int half = 0; half < 2; half++) {
                const int r = row0 + wm + mt * 16 + r0l + half * 8;
                if (r < cnt) {
                    float v0 = acc[mt][nt][half * 2 + 0];
                    float v1 = acc[mt][nt][half * 2 + 1];
                    *(float2*)(g_Y + (size_t)(base + r) * DDIM + fc) = make_float2(v0, v1);
                }
            }
        }
    }
}

// ---------------- combine: out[t] = w1*(y1+b2[e1]) + w2*(y2+b2[e2]) ----------
__global__ void combine_kernel(const float* __restrict__ b2,
                               float* __restrict__ out) {
    const int idx = blockIdx.x * blockDim.x + threadIdx.x;
    const int t = idx >> 8;       // DDIM/4 = 256 float4 per token
    const int c4 = idx & 255;
    int4 a = g_assign[t];
    float2 w = g_tw[t];
    const int s1 = g_base[a.x] + a.y;
    const int s2 = g_base[a.z] + a.w;
    float4 y1 = *(const float4*)(g_Y + (size_t)s1 * DDIM + c4 * 4);
    float4 y2 = *(const float4*)(g_Y + (size_t)s2 * DDIM + c4 * 4);
    float4 v1 = *(const float4*)(b2 + (size_t)a.x * DDIM + c4 * 4);
    float4 v2 = *(const float4*)(b2 + (size_t)a.z * DDIM + c4 * 4);
    float4 o;
    o.x = w.x * (y1.x + v1.x) + w.y * (y2.x + v2.x);
    o.y = w.x * (y1.y + v1.y) + w.y * (y2.y + v2.y);
    o.z = w.x * (y1.z + v1.z) + w.y * (y2.z + v2.z);
    o.w = w.x * (y1.w + v1.w) + w.y * (y2.w + v2.w);
    ((float4*)out)[idx] = o;
}

// ---------------- launch -----------------------------------------------------
extern "C" void kernel_launch(void* const* d_in, const int* in_sizes, int n_in,
                              void* d_out, int out_size) {
    const float* x  = (const float*)d_in[0];
    const float* Wr = (const float*)d_in[1];
    const float* W1 = (const float*)d_in[2];
    const float* b1 = (const float*)d_in[3];
    const float* W2 = (const float*)d_in[4];
    const float* b2 = (const float*)d_in[5];
    float* out = (float*)d_out;

    init_counts_kernel<<<1, 32>>>();
    router_kernel<<<T_TOKENS / 8, 256>>>(x, Wr);
    prefix_kernel<<<1, 32>>>();

    dim3 grid(DDIM / BN, T_TOKENS / BM, NEXP);
    gemm1_kernel<<<grid, 256>>>(x, W1, b1);
    gemm2_kernel<<<grid, 256>>>(W2);

    combine_kernel<<<(T_TOKENS * DDIM / 4) / 256, 256>>>(b2, out);
}